// round 1
// baseline (speedup 1.0000x reference)
#include <cuda_runtime.h>
#include <math.h>

// Problem constants
#define BB 2
#define SS 2048
#define DD 1024
#define HH 16
#define HDIM 64
#define DFF 4096
#define MROWS (BB * SS)   // 4096

// ---------------------------------------------------------------------------
// Scratch (device globals; no allocations allowed)
// ---------------------------------------------------------------------------
__device__ float g_h  [MROWS * DD];   // LN output
__device__ float g_q  [MROWS * DD];
__device__ float g_k  [MROWS * DD];
__device__ float g_v  [MROWS * DD];
__device__ float g_ctx[MROWS * DD];
__device__ float g_x2 [MROWS * DD];   // x after first residual
__device__ float g_mid[MROWS * DFF];  // GELU(h@W1+b1)

// ---------------------------------------------------------------------------
// LayerNorm: one block (256 threads) per row of 1024 floats
// ---------------------------------------------------------------------------
__global__ void ln_kernel(const float* __restrict__ x,
                          const float* __restrict__ gamma,
                          const float* __restrict__ beta,
                          float* __restrict__ y) {
    int row = blockIdx.x;
    int tid = threadIdx.x;  // 256
    const float4* xr = reinterpret_cast<const float4*>(x + (size_t)row * DD);
    float4 v = xr[tid];

    float s  = v.x + v.y + v.z + v.w;
    float sq = v.x * v.x + v.y * v.y + v.z * v.z + v.w * v.w;

    // warp reduce
    for (int o = 16; o > 0; o >>= 1) {
        s  += __shfl_down_sync(0xffffffffu, s,  o);
        sq += __shfl_down_sync(0xffffffffu, sq, o);
    }
    __shared__ float ws[8], wq[8];
    int lane = tid & 31, warp = tid >> 5;
    if (lane == 0) { ws[warp] = s; wq[warp] = sq; }
    __syncthreads();
    __shared__ float mu_s, rstd_s;
    if (tid == 0) {
        float ts = 0.f, tq = 0.f;
        #pragma unroll
        for (int i = 0; i < 8; i++) { ts += ws[i]; tq += wq[i]; }
        float mu  = ts * (1.0f / DD);
        float var = tq * (1.0f / DD) - mu * mu;
        mu_s = mu;
        rstd_s = rsqrtf(var + 1e-5f);
    }
    __syncthreads();
    float mu = mu_s, r = rstd_s;

    float4 g4 = reinterpret_cast<const float4*>(gamma)[tid];
    float4 b4 = reinterpret_cast<const float4*>(beta)[tid];
    float4 o;
    o.x = (v.x - mu) * r * g4.x + b4.x;
    o.y = (v.y - mu) * r * g4.y + b4.y;
    o.z = (v.z - mu) * r * g4.z + b4.z;
    o.w = (v.w - mu) * r * g4.w + b4.w;
    reinterpret_cast<float4*>(y + (size_t)row * DD)[tid] = o;
}

// ---------------------------------------------------------------------------
// Tiled fp32 SGEMM: C[M,N] = A[M,K] @ B[K,N] (+bias)(gelu)(+res)
// BM=BN=64, BK=16, 256 threads, 4x4 microtile.
// ---------------------------------------------------------------------------
__device__ __forceinline__ float gelu_exact(float v) {
    return 0.5f * v * (1.0f + erff(v * 0.70710678118654752f));
}

__global__ void gemm_kernel(const float* __restrict__ A,
                            const float* __restrict__ Bm,
                            float* __restrict__ C,
                            int M, int N, int K,
                            const float* __restrict__ bias,
                            const float* __restrict__ res,
                            int dogelu) {
    const int BM = 64, BN = 64, BK = 16;
    __shared__ float As[BK][BM];
    __shared__ float Bs[BK][BN];

    int tid = threadIdx.x;          // 0..255
    int tx = tid & 15;              // 0..15  (N direction)
    int ty = tid >> 4;              // 0..15  (M direction)
    int m0 = blockIdx.y * BM;
    int n0 = blockIdx.x * BN;

    float acc[4][4];
    #pragma unroll
    for (int i = 0; i < 4; i++)
        #pragma unroll
        for (int j = 0; j < 4; j++) acc[i][j] = 0.f;

    for (int k0 = 0; k0 < K; k0 += BK) {
        // load A tile 64x16 -> As[k][m]
        #pragma unroll
        for (int j = 0; j < 4; j++) {
            int e = tid + 256 * j;      // 0..1023
            int r = e >> 4;             // /16
            int c = e & 15;
            As[c][r] = A[(size_t)(m0 + r) * K + (k0 + c)];
        }
        // load B tile 16x64 -> Bs[k][n]
        #pragma unroll
        for (int j = 0; j < 4; j++) {
            int e = tid + 256 * j;
            int r = e >> 6;             // /64
            int c = e & 63;
            Bs[r][c] = Bm[(size_t)(k0 + r) * N + (n0 + c)];
        }
        __syncthreads();

        #pragma unroll
        for (int kk = 0; kk < BK; kk++) {
            float a[4], b[4];
            #pragma unroll
            for (int i = 0; i < 4; i++) a[i] = As[kk][ty * 4 + i];
            #pragma unroll
            for (int j = 0; j < 4; j++) b[j] = Bs[kk][tx * 4 + j];
            #pragma unroll
            for (int i = 0; i < 4; i++)
                #pragma unroll
                for (int j = 0; j < 4; j++)
                    acc[i][j] = fmaf(a[i], b[j], acc[i][j]);
        }
        __syncthreads();
    }

    #pragma unroll
    for (int i = 0; i < 4; i++) {
        int m = m0 + ty * 4 + i;
        #pragma unroll
        for (int j = 0; j < 4; j++) {
            int n = n0 + tx * 4 + j;
            float c = acc[i][j];
            if (bias) c += bias[n];
            if (dogelu) c = gelu_exact(c);
            if (res) c += res[(size_t)m * N + n];
            C[(size_t)m * N + n] = c;
        }
    }
}

// ---------------------------------------------------------------------------
// Causal attention: one block (256 threads) per (b, h, q-row).
// Q/K/V layout: [B*S, D] with head h at columns [h*64, h*64+64).
// Scores staged in smem (<=2048), softmax, then PV with 4-way t-split.
// ---------------------------------------------------------------------------
__global__ void attn_kernel(const float* __restrict__ Q,
                            const float* __restrict__ K,
                            const float* __restrict__ V,
                            float* __restrict__ O) {
    int idx = blockIdx.x;
    int qs = idx % SS;
    int h  = (idx / SS) % HH;
    int b  = idx / (SS * HH);
    int nk = qs + 1;
    int tid = threadIdx.x;   // 256

    __shared__ float qv[HDIM];
    __shared__ float sc[SS];
    __shared__ float red[256];

    const float* qrow = Q + ((size_t)(b * SS + qs)) * DD + h * HDIM;
    if (tid < HDIM) qv[tid] = qrow[tid];
    __syncthreads();

    const float scale = 0.125f;  // 1/sqrt(64)

    // Pass 1: scores + running max
    float lmax = -INFINITY;
    for (int t = tid; t < nk; t += 256) {
        const float* kr = K + ((size_t)(b * SS + t)) * DD + h * HDIM;
        float s = 0.f;
        #pragma unroll
        for (int d = 0; d < HDIM; d++) s = fmaf(qv[d], kr[d], s);
        s *= scale;
        sc[t] = s;
        lmax = fmaxf(lmax, s);
    }
    // block max
    red[tid] = lmax;
    __syncthreads();
    for (int o = 128; o > 0; o >>= 1) {
        if (tid < o) red[tid] = fmaxf(red[tid], red[tid + o]);
        __syncthreads();
    }
    float m = red[0];
    __syncthreads();

    // exp + sum
    float lsum = 0.f;
    for (int t = tid; t < nk; t += 256) {
        float e = __expf(sc[t] - m);
        sc[t] = e;
        lsum += e;
    }
    red[tid] = lsum;
    __syncthreads();
    for (int o = 128; o > 0; o >>= 1) {
        if (tid < o) red[tid] += red[tid + o];
        __syncthreads();
    }
    float inv = 1.0f / red[0];
    __syncthreads();

    // Pass 2: O[d] = sum_t p[t] * V[t][d]; 4 groups of 64 threads over t
    int g = tid >> 6;      // 0..3
    int d = tid & 63;
    float acc = 0.f;
    for (int t = g; t < nk; t += 4) {
        acc = fmaf(sc[t], V[((size_t)(b * SS + t)) * DD + h * HDIM + d], acc);
    }
    red[tid] = acc;
    __syncthreads();
    if (g == 0) {
        float o = red[d] + red[64 + d] + red[128 + d] + red[192 + d];
        O[((size_t)(b * SS + qs)) * DD + h * HDIM + d] = o * inv;
    }
}

// ---------------------------------------------------------------------------
// Launch
// ---------------------------------------------------------------------------
extern "C" void kernel_launch(void* const* d_in, const int* in_sizes, int n_in,
                              void* d_out, int out_size) {
    const float* x     = (const float*)d_in[0];
    const float* ln1_g = (const float*)d_in[1];
    const float* ln1_b = (const float*)d_in[2];
    const float* Wq    = (const float*)d_in[3];
    const float* Wk    = (const float*)d_in[4];
    const float* Wv    = (const float*)d_in[5];
    const float* Wo    = (const float*)d_in[6];
    const float* bo    = (const float*)d_in[7];
    const float* ln2_g = (const float*)d_in[8];
    const float* ln2_b = (const float*)d_in[9];
    const float* W1    = (const float*)d_in[10];
    const float* b1    = (const float*)d_in[11];
    const float* W2    = (const float*)d_in[12];
    const float* b2    = (const float*)d_in[13];
    float* out = (float*)d_out;

    float *h, *q, *k, *v, *ctx, *x2, *mid;
    cudaGetSymbolAddress((void**)&h,   g_h);
    cudaGetSymbolAddress((void**)&q,   g_q);
    cudaGetSymbolAddress((void**)&k,   g_k);
    cudaGetSymbolAddress((void**)&v,   g_v);
    cudaGetSymbolAddress((void**)&ctx, g_ctx);
    cudaGetSymbolAddress((void**)&x2,  g_x2);
    cudaGetSymbolAddress((void**)&mid, g_mid);

    const int M = MROWS;

    // 1. LN1
    ln_kernel<<<M, 256>>>(x, ln1_g, ln1_b, h);

    // 2. QKV projections
    dim3 gDD(DD / 64, M / 64);
    gemm_kernel<<<gDD, 256>>>(h, Wq, q, M, DD, DD, nullptr, nullptr, 0);
    gemm_kernel<<<gDD, 256>>>(h, Wk, k, M, DD, DD, nullptr, nullptr, 0);
    gemm_kernel<<<gDD, 256>>>(h, Wv, v, M, DD, DD, nullptr, nullptr, 0);

    // 3. causal attention
    attn_kernel<<<BB * HH * SS, 256>>>(q, k, v, ctx);

    // 4. output projection + bias + residual(x) -> x2
    gemm_kernel<<<gDD, 256>>>(ctx, Wo, x2, M, DD, DD, bo, x, 0);

    // 5. LN2
    ln_kernel<<<M, 256>>>(x2, ln2_g, ln2_b, h);

    // 6. W1 + b1 + exact GELU -> mid
    dim3 gFF(DFF / 64, M / 64);
    gemm_kernel<<<gFF, 256>>>(h, W1, mid, M, DFF, DD, b1, nullptr, 1);

    // 7. W2 + b2 + residual(x2) -> out
    gemm_kernel<<<gDD, 256>>>(mid, W2, out, M, DD, DFF, b2, x2, 0);
}

// round 2
// speedup vs baseline: 6.3728x; 6.3728x over previous
#include <cuda_runtime.h>
#include <math.h>

// Problem constants
#define BB 2
#define SS 2048
#define DD 1024
#define HH 16
#define HDIM 64
#define DFF 4096
#define MROWS (BB * SS)   // 4096

// ---------------------------------------------------------------------------
// Scratch (device globals; no allocations allowed)
// ---------------------------------------------------------------------------
__device__ float g_h  [MROWS * DD];   // LN output
__device__ float g_q  [MROWS * DD];
__device__ float g_k  [MROWS * DD];
__device__ float g_v  [MROWS * DD];
__device__ float g_ctx[MROWS * DD];
__device__ float g_x2 [MROWS * DD];   // x after first residual
__device__ float g_mid[MROWS * DFF];  // GELU(h@W1+b1)

// ---------------------------------------------------------------------------
// LayerNorm: one block (256 threads) per row of 1024 floats
// ---------------------------------------------------------------------------
__global__ void ln_kernel(const float* __restrict__ x,
                          const float* __restrict__ gamma,
                          const float* __restrict__ beta,
                          float* __restrict__ y) {
    int row = blockIdx.x;
    int tid = threadIdx.x;  // 256
    const float4* xr = reinterpret_cast<const float4*>(x + (size_t)row * DD);
    float4 v = xr[tid];

    float s  = v.x + v.y + v.z + v.w;
    float sq = v.x * v.x + v.y * v.y + v.z * v.z + v.w * v.w;

    for (int o = 16; o > 0; o >>= 1) {
        s  += __shfl_down_sync(0xffffffffu, s,  o);
        sq += __shfl_down_sync(0xffffffffu, sq, o);
    }
    __shared__ float ws[8], wq[8];
    int lane = tid & 31, warp = tid >> 5;
    if (lane == 0) { ws[warp] = s; wq[warp] = sq; }
    __syncthreads();
    __shared__ float mu_s, rstd_s;
    if (tid == 0) {
        float ts = 0.f, tq = 0.f;
        #pragma unroll
        for (int i = 0; i < 8; i++) { ts += ws[i]; tq += wq[i]; }
        float mu  = ts * (1.0f / DD);
        float var = tq * (1.0f / DD) - mu * mu;
        mu_s = mu;
        rstd_s = rsqrtf(var + 1e-5f);
    }
    __syncthreads();
    float mu = mu_s, r = rstd_s;

    float4 g4 = reinterpret_cast<const float4*>(gamma)[tid];
    float4 b4 = reinterpret_cast<const float4*>(beta)[tid];
    float4 o;
    o.x = (v.x - mu) * r * g4.x + b4.x;
    o.y = (v.y - mu) * r * g4.y + b4.y;
    o.z = (v.z - mu) * r * g4.z + b4.z;
    o.w = (v.w - mu) * r * g4.w + b4.w;
    reinterpret_cast<float4*>(y + (size_t)row * DD)[tid] = o;
}

// ---------------------------------------------------------------------------
// SGEMM core: C[M,N] = A[M,K] @ B[K,N] (+bias)(gelu)(+res)
// BM=BN=128, BK=16, 256 threads, 8x8 microtile, float4 smem traffic.
// ---------------------------------------------------------------------------
__device__ __forceinline__ float gelu_exact(float v) {
    return 0.5f * v * (1.0f + erff(v * 0.70710678118654752f));
}

__device__ __forceinline__ void gemm_body(const float* __restrict__ A,
                                          const float* __restrict__ Bm,
                                          float* __restrict__ C,
                                          int M, int N, int K,
                                          const float* __restrict__ bias,
                                          const float* __restrict__ res,
                                          int dogelu) {
    __shared__ float As[16][132];   // [k][m], padded
    __shared__ float Bs[16][132];   // [k][n], padded

    const int tid = threadIdx.x;        // 0..255
    const int tx = tid & 15;            // N dir
    const int ty = tid >> 4;            // M dir
    const int m0 = blockIdx.y * 128;
    const int n0 = blockIdx.x * 128;

    float acc[8][8];
    #pragma unroll
    for (int i = 0; i < 8; i++)
        #pragma unroll
        for (int j = 0; j < 8; j++) acc[i][j] = 0.f;

    for (int k0 = 0; k0 < K; k0 += 16) {
        // A tile: 128x16 = 512 float4, 2 per thread, store k-major
        #pragma unroll
        for (int l = 0; l < 2; l++) {
            int f = tid + 256 * l;
            int row = f >> 2;           // 0..127
            int c4  = f & 3;            // 0..3
            float4 v = *(const float4*)(A + (size_t)(m0 + row) * K + k0 + c4 * 4);
            As[c4 * 4 + 0][row] = v.x;
            As[c4 * 4 + 1][row] = v.y;
            As[c4 * 4 + 2][row] = v.z;
            As[c4 * 4 + 3][row] = v.w;
        }
        // B tile: 16x128 = 512 float4, straight
        #pragma unroll
        for (int l = 0; l < 2; l++) {
            int f = tid + 256 * l;
            int row = f >> 5;           // 0..15
            int c4  = f & 31;           // 0..31
            float4 v = *(const float4*)(Bm + (size_t)(k0 + row) * N + n0 + c4 * 4);
            *(float4*)(&Bs[row][c4 * 4]) = v;
        }
        __syncthreads();

        #pragma unroll
        for (int kk = 0; kk < 16; kk++) {
            float a[8], b[8];
            *(float4*)(a)     = *(const float4*)(&As[kk][ty * 8]);
            *(float4*)(a + 4) = *(const float4*)(&As[kk][ty * 8 + 4]);
            *(float4*)(b)     = *(const float4*)(&Bs[kk][tx * 8]);
            *(float4*)(b + 4) = *(const float4*)(&Bs[kk][tx * 8 + 4]);
            #pragma unroll
            for (int i = 0; i < 8; i++)
                #pragma unroll
                for (int j = 0; j < 8; j++)
                    acc[i][j] = fmaf(a[i], b[j], acc[i][j]);
        }
        __syncthreads();
    }

    float bvals[8];
    if (bias) {
        *(float4*)(bvals)     = *(const float4*)(bias + n0 + tx * 8);
        *(float4*)(bvals + 4) = *(const float4*)(bias + n0 + tx * 8 + 4);
    }

    #pragma unroll
    for (int i = 0; i < 8; i++) {
        int m = m0 + ty * 8 + i;
        float v[8];
        #pragma unroll
        for (int j = 0; j < 8; j++) {
            float c = acc[i][j];
            if (bias) c += bvals[j];
            if (dogelu) c = gelu_exact(c);
            v[j] = c;
        }
        if (res) {
            float4 r0 = *(const float4*)(res + (size_t)m * N + n0 + tx * 8);
            float4 r1 = *(const float4*)(res + (size_t)m * N + n0 + tx * 8 + 4);
            v[0] += r0.x; v[1] += r0.y; v[2] += r0.z; v[3] += r0.w;
            v[4] += r1.x; v[5] += r1.y; v[6] += r1.z; v[7] += r1.w;
        }
        *(float4*)(C + (size_t)m * N + n0 + tx * 8)     = *(float4*)(v);
        *(float4*)(C + (size_t)m * N + n0 + tx * 8 + 4) = *(float4*)(v + 4);
    }
}

__global__ void __launch_bounds__(256)
gemm_kernel(const float* __restrict__ A, const float* __restrict__ Bm,
            float* __restrict__ C, int M, int N, int K,
            const float* __restrict__ bias, const float* __restrict__ res,
            int dogelu) {
    gemm_body(A, Bm, C, M, N, K, bias, res, dogelu);
}

__global__ void __launch_bounds__(256)
gemm_qkv_kernel(const float* __restrict__ A,
                const float* __restrict__ Wq, const float* __restrict__ Wk,
                const float* __restrict__ Wv,
                float* __restrict__ q, float* __restrict__ k,
                float* __restrict__ v, int M, int N, int K) {
    const float* Bm = (blockIdx.z == 0) ? Wq : (blockIdx.z == 1) ? Wk : Wv;
    float* C        = (blockIdx.z == 0) ? q  : (blockIdx.z == 1) ? k  : v;
    gemm_body(A, Bm, C, M, N, K, nullptr, nullptr, 0);
}

// ---------------------------------------------------------------------------
// Flash attention (fp32 SIMT): block = (b,h, 128-query tile), 256 threads.
// K/V tiles of 64 rows in smem; online softmax; 8x4 microtiles, float4 LDS.
// smem: Qt[64][132] + Kt[64][68] + Vs[64][68] + Pt[64][132] = 100 KB dynamic.
// ---------------------------------------------------------------------------
#define ATT_SMEM (64*132*4 + 64*68*4 + 64*68*4 + 64*132*4)

__global__ void __launch_bounds__(256, 2)
flash_attn_kernel(const float* __restrict__ Q, const float* __restrict__ K,
                  const float* __restrict__ V, float* __restrict__ O) {
    extern __shared__ float sm[];
    float* Qt = sm;                    // [d=64][q=128] pitch 132
    float* Kt = Qt + 64 * 132;         // [d=64][k=64]  pitch 68
    float* Vs = Kt + 64 * 68;          // [k=64][d=64]  pitch 68
    float* Pt = Vs + 64 * 68;          // [k=64][q=128] pitch 132

    const int tid = threadIdx.x;
    const int tx = tid & 15;           // k (S phase) / d (PV phase)
    const int ty = tid >> 4;           // q
    const int qt = blockIdx.x;         // 0..15 (128-query tiles)
    const int h  = blockIdx.y & 15;
    const int b  = blockIdx.y >> 4;
    const size_t base = ((size_t)b * SS) * DD + (size_t)h * HDIM;

    // Load Q tile transposed -> Qt[d][q]
    #pragma unroll
    for (int l = 0; l < 8; l++) {
        int f = tid + 256 * l;
        int row = f >> 4;              // 0..127
        int c4  = f & 15;              // 0..15
        float4 v = *(const float4*)(Q + base + (size_t)(qt * 128 + row) * DD + c4 * 4);
        Qt[(c4 * 4 + 0) * 132 + row] = v.x;
        Qt[(c4 * 4 + 1) * 132 + row] = v.y;
        Qt[(c4 * 4 + 2) * 132 + row] = v.z;
        Qt[(c4 * 4 + 3) * 132 + row] = v.w;
    }

    float m_i[8], l_i[8], o[8][4];
    #pragma unroll
    for (int i = 0; i < 8; i++) {
        m_i[i] = -1e30f; l_i[i] = 0.f;
        #pragma unroll
        for (int j = 0; j < 4; j++) o[i][j] = 0.f;
    }
    __syncthreads();

    const int ktmax = 2 * qt + 1;
    for (int kt = 0; kt <= ktmax; kt++) {
        // Load K transposed -> Kt[d][k], V straight -> Vs[k][d]
        #pragma unroll
        for (int l = 0; l < 4; l++) {
            int f = tid + 256 * l;
            int row = f >> 4;          // 0..63
            int c4  = f & 15;
            float4 kv = *(const float4*)(K + base + (size_t)(kt * 64 + row) * DD + c4 * 4);
            Kt[(c4 * 4 + 0) * 68 + row] = kv.x;
            Kt[(c4 * 4 + 1) * 68 + row] = kv.y;
            Kt[(c4 * 4 + 2) * 68 + row] = kv.z;
            Kt[(c4 * 4 + 3) * 68 + row] = kv.w;
            float4 vv = *(const float4*)(V + base + (size_t)(kt * 64 + row) * DD + c4 * 4);
            *(float4*)(&Vs[row * 68 + c4 * 4]) = vv;
        }
        __syncthreads();

        // S = Q K^T : 8 q-rows x 4 k-cols per thread
        float s[8][4];
        #pragma unroll
        for (int i = 0; i < 8; i++)
            #pragma unroll
            for (int j = 0; j < 4; j++) s[i][j] = 0.f;

        #pragma unroll
        for (int d = 0; d < 64; d++) {
            float a[8];
            *(float4*)(a)     = *(const float4*)(&Qt[d * 132 + ty * 8]);
            *(float4*)(a + 4) = *(const float4*)(&Qt[d * 132 + ty * 8 + 4]);
            float4 bb = *(const float4*)(&Kt[d * 68 + tx * 4]);
            #pragma unroll
            for (int i = 0; i < 8; i++) {
                s[i][0] = fmaf(a[i], bb.x, s[i][0]);
                s[i][1] = fmaf(a[i], bb.y, s[i][1]);
                s[i][2] = fmaf(a[i], bb.z, s[i][2]);
                s[i][3] = fmaf(a[i], bb.w, s[i][3]);
            }
        }

        const bool needmask = (kt >= 2 * qt);

        // online softmax + write P transposed
        #pragma unroll
        for (int i = 0; i < 8; i++) {
            int qg = qt * 128 + ty * 8 + i;
            float rmax = -1e30f;
            #pragma unroll
            for (int j = 0; j < 4; j++) {
                float sv = s[i][j] * 0.125f;
                if (needmask && (kt * 64 + tx * 4 + j > qg)) sv = -1e30f;
                s[i][j] = sv;
                rmax = fmaxf(rmax, sv);
            }
            #pragma unroll
            for (int off = 1; off < 16; off <<= 1)
                rmax = fmaxf(rmax, __shfl_xor_sync(0xffffffffu, rmax, off));
            float mnew = fmaxf(m_i[i], rmax);
            float sc = __expf(m_i[i] - mnew);
            float rsum = 0.f;
            #pragma unroll
            for (int j = 0; j < 4; j++) {
                float p = __expf(s[i][j] - mnew);
                s[i][j] = p;
                rsum += p;
            }
            #pragma unroll
            for (int off = 1; off < 16; off <<= 1)
                rsum += __shfl_xor_sync(0xffffffffu, rsum, off);
            l_i[i] = l_i[i] * sc + rsum;
            m_i[i] = mnew;
            #pragma unroll
            for (int j = 0; j < 4; j++) {
                o[i][j] *= sc;
                Pt[(tx * 4 + j) * 132 + ty * 8 + i] = s[i][j];
            }
        }
        __syncthreads();

        // O += P @ V : 8 q-rows x 4 d-cols per thread
        #pragma unroll
        for (int kk = 0; kk < 64; kk++) {
            float a[8];
            *(float4*)(a)     = *(const float4*)(&Pt[kk * 132 + ty * 8]);
            *(float4*)(a + 4) = *(const float4*)(&Pt[kk * 132 + ty * 8 + 4]);
            float4 bb = *(const float4*)(&Vs[kk * 68 + tx * 4]);
            #pragma unroll
            for (int i = 0; i < 8; i++) {
                o[i][0] = fmaf(a[i], bb.x, o[i][0]);
                o[i][1] = fmaf(a[i], bb.y, o[i][1]);
                o[i][2] = fmaf(a[i], bb.z, o[i][2]);
                o[i][3] = fmaf(a[i], bb.w, o[i][3]);
            }
        }
        __syncthreads();
    }

    #pragma unroll
    for (int i = 0; i < 8; i++) {
        float inv = 1.0f / l_i[i];
        float4 ov;
        ov.x = o[i][0] * inv; ov.y = o[i][1] * inv;
        ov.z = o[i][2] * inv; ov.w = o[i][3] * inv;
        *(float4*)(O + base + (size_t)(qt * 128 + ty * 8 + i) * DD + tx * 4) = ov;
    }
}

// ---------------------------------------------------------------------------
// Launch
// ---------------------------------------------------------------------------
extern "C" void kernel_launch(void* const* d_in, const int* in_sizes, int n_in,
                              void* d_out, int out_size) {
    const float* x     = (const float*)d_in[0];
    const float* ln1_g = (const float*)d_in[1];
    const float* ln1_b = (const float*)d_in[2];
    const float* Wq    = (const float*)d_in[3];
    const float* Wk    = (const float*)d_in[4];
    const float* Wv    = (const float*)d_in[5];
    const float* Wo    = (const float*)d_in[6];
    const float* bo    = (const float*)d_in[7];
    const float* ln2_g = (const float*)d_in[8];
    const float* ln2_b = (const float*)d_in[9];
    const float* W1    = (const float*)d_in[10];
    const float* b1    = (const float*)d_in[11];
    const float* W2    = (const float*)d_in[12];
    const float* b2    = (const float*)d_in[13];
    float* out = (float*)d_out;

    float *h, *q, *k, *v, *ctx, *x2, *mid;
    cudaGetSymbolAddress((void**)&h,   g_h);
    cudaGetSymbolAddress((void**)&q,   g_q);
    cudaGetSymbolAddress((void**)&k,   g_k);
    cudaGetSymbolAddress((void**)&v,   g_v);
    cudaGetSymbolAddress((void**)&ctx, g_ctx);
    cudaGetSymbolAddress((void**)&x2,  g_x2);
    cudaGetSymbolAddress((void**)&mid, g_mid);

    static int attr_set = 0;
    if (!attr_set) {
        cudaFuncSetAttribute(flash_attn_kernel,
                             cudaFuncAttributeMaxDynamicSharedMemorySize, ATT_SMEM);
        attr_set = 1;
    }

    const int M = MROWS;

    // 1. LN1
    ln_kernel<<<M, 256>>>(x, ln1_g, ln1_b, h);

    // 2. QKV projections (fused z-launch)
    dim3 gQKV(DD / 128, M / 128, 3);
    gemm_qkv_kernel<<<gQKV, 256>>>(h, Wq, Wk, Wv, q, k, v, M, DD, DD);

    // 3. causal flash attention
    dim3 gA(SS / 128, BB * HH);
    flash_attn_kernel<<<gA, 256, ATT_SMEM>>>(q, k, v, ctx);

    // 4. output projection + bias + residual(x) -> x2
    dim3 gDD(DD / 128, M / 128);
    gemm_kernel<<<gDD, 256>>>(ctx, Wo, x2, M, DD, DD, bo, x, 0);

    // 5. LN2
    ln_kernel<<<M, 256>>>(x2, ln2_g, ln2_b, h);

    // 6. W1 + b1 + exact GELU -> mid
    dim3 gFF(DFF / 128, M / 128);
    gemm_kernel<<<gFF, 256>>>(h, W1, mid, M, DFF, DD, b1, nullptr, 1);

    // 7. W2 + b2 + residual(x2) -> out
    gemm_kernel<<<gDD, 256>>>(mid, W2, out, M, DD, DFF, b2, x2, 0);
}

// round 4
// speedup vs baseline: 11.5445x; 1.8115x over previous
#include <cuda_runtime.h>
#include <cuda_bf16.h>
#include <math.h>
#include <cstdint>

// Problem constants
#define BB 2
#define SS 2048
#define DD 1024
#define HH 16
#define HDIM 64
#define DFF 4096
#define MROWS (BB * SS)   // 4096

// ---------------------------------------------------------------------------
// PTX helpers (non-arch-suffixed features only: ldmatrix, mma.sync, cp.async)
// ---------------------------------------------------------------------------
__device__ __forceinline__ uint32_t smem_to_u32(const void* smem_ptr) {
    uint32_t addr;
    asm("{ .reg .u64 tmp; cvta.to.shared.u64 tmp, %1; cvt.u32.u64 %0, tmp; }"
        : "=r"(addr) : "l"(smem_ptr));
    return addr;
}

__device__ __forceinline__ void ldmx4(uint32_t* r, uint32_t addr) {
    asm volatile("ldmatrix.sync.aligned.m8n8.x4.shared.b16 {%0,%1,%2,%3}, [%4];"
        : "=r"(r[0]), "=r"(r[1]), "=r"(r[2]), "=r"(r[3]) : "r"(addr));
}

__device__ __forceinline__ void mma16816(float* c, const uint32_t* a,
                                         uint32_t b0, uint32_t b1) {
    asm volatile(
        "mma.sync.aligned.m16n8k16.row.col.f32.bf16.bf16.f32 "
        "{%0,%1,%2,%3}, {%4,%5,%6,%7}, {%8,%9}, {%0,%1,%2,%3};"
        : "+f"(c[0]), "+f"(c[1]), "+f"(c[2]), "+f"(c[3])
        : "r"(a[0]), "r"(a[1]), "r"(a[2]), "r"(a[3]), "r"(b0), "r"(b1));
}

#define CP_ASYNC16(smem_u32, gptr) \
    asm volatile("cp.async.cg.shared.global [%0], [%1], 16;" \
        :: "r"(smem_u32), "l"(gptr))
#define CP_ASYNC_COMMIT() asm volatile("cp.async.commit_group;" ::: "memory")
#define CP_ASYNC_WAIT0()  asm volatile("cp.async.wait_group 0;" ::: "memory")

// ---------------------------------------------------------------------------
// Scratch (device globals; no allocations allowed)
// ---------------------------------------------------------------------------
__device__ float g_h  [MROWS * DD];
__device__ float g_q  [MROWS * DD];
__device__ float g_k  [MROWS * DD];
__device__ float g_v  [MROWS * DD];
__device__ float g_ctx[MROWS * DD];
__device__ float g_x2 [MROWS * DD];
__device__ float g_mid[MROWS * DFF];

// Transposed + bf16x2-split weights: [N,K]
__device__ __nv_bfloat16 g_wqh[DD * DD],  g_wql[DD * DD];
__device__ __nv_bfloat16 g_wkh[DD * DD],  g_wkl[DD * DD];
__device__ __nv_bfloat16 g_wvh[DD * DD],  g_wvl[DD * DD];
__device__ __nv_bfloat16 g_woh[DD * DD],  g_wol[DD * DD];
__device__ __nv_bfloat16 g_w1h[DD * DFF], g_w1l[DD * DFF];
__device__ __nv_bfloat16 g_w2h[DFF * DD], g_w2l[DFF * DD];

// ---------------------------------------------------------------------------
// Weight transpose + bf16x2 split: W[K,N] fp32 -> Th,Tl [N,K] bf16
// ---------------------------------------------------------------------------
__global__ void wsplit_kernel(const float* __restrict__ W,
                              __nv_bfloat16* __restrict__ Th,
                              __nv_bfloat16* __restrict__ Tl,
                              int K, int N) {
    __shared__ float tile[32][33];
    int bx = blockIdx.x;  // N/32
    int by = blockIdx.y;  // K/32
    int tx = threadIdx.x; // 32
    int ty = threadIdx.y; // 8
    #pragma unroll
    for (int i = 0; i < 4; i++)
        tile[ty + 8 * i][tx] = W[(size_t)(by * 32 + ty + 8 * i) * N + bx * 32 + tx];
    __syncthreads();
    #pragma unroll
    for (int i = 0; i < 4; i++) {
        float v = tile[tx][ty + 8 * i];
        __nv_bfloat16 h = __float2bfloat16(v);
        __nv_bfloat16 l = __float2bfloat16(v - __bfloat162float(h));
        size_t o = (size_t)(bx * 32 + ty + 8 * i) * K + by * 32 + tx;
        Th[o] = h; Tl[o] = l;
    }
}

// ---------------------------------------------------------------------------
// LayerNorm
// ---------------------------------------------------------------------------
__global__ void ln_kernel(const float* __restrict__ x,
                          const float* __restrict__ gamma,
                          const float* __restrict__ beta,
                          float* __restrict__ y) {
    int row = blockIdx.x;
    int tid = threadIdx.x;  // 256
    const float4* xr = reinterpret_cast<const float4*>(x + (size_t)row * DD);
    float4 v = xr[tid];

    float s  = v.x + v.y + v.z + v.w;
    float sq = v.x * v.x + v.y * v.y + v.z * v.z + v.w * v.w;
    for (int o = 16; o > 0; o >>= 1) {
        s  += __shfl_down_sync(0xffffffffu, s,  o);
        sq += __shfl_down_sync(0xffffffffu, sq, o);
    }
    __shared__ float ws[8], wq[8];
    int lane = tid & 31, warp = tid >> 5;
    if (lane == 0) { ws[warp] = s; wq[warp] = sq; }
    __syncthreads();
    __shared__ float mu_s, rstd_s;
    if (tid == 0) {
        float ts = 0.f, tq = 0.f;
        #pragma unroll
        for (int i = 0; i < 8; i++) { ts += ws[i]; tq += wq[i]; }
        float mu  = ts * (1.0f / DD);
        float var = tq * (1.0f / DD) - mu * mu;
        mu_s = mu;
        rstd_s = rsqrtf(var + 1e-5f);
    }
    __syncthreads();
    float mu = mu_s, r = rstd_s;

    float4 g4 = reinterpret_cast<const float4*>(gamma)[tid];
    float4 b4 = reinterpret_cast<const float4*>(beta)[tid];
    float4 o;
    o.x = (v.x - mu) * r * g4.x + b4.x;
    o.y = (v.y - mu) * r * g4.y + b4.y;
    o.z = (v.z - mu) * r * g4.z + b4.z;
    o.w = (v.w - mu) * r * g4.w + b4.w;
    reinterpret_cast<float4*>(y + (size_t)row * DD)[tid] = o;
}

__device__ __forceinline__ float gelu_exact(float v) {
    return 0.5f * v * (1.0f + erff(v * 0.70710678118654752f));
}

// ---------------------------------------------------------------------------
// mma.sync bf16x2 GEMM: C[M,N] = A[M,K](fp32) @ (Bh+Bl)[N,K]^T (+bias)(gelu)(+res)
// CTA 128x128, BK=64, 8 warps (2M x 4N, warp tile 64x32), double-buffered smem.
// Stage layout (64KB): Ah[128x128B] Al Bh Bl, SW128 swizzle on 128B rows.
// ---------------------------------------------------------------------------
#define STAGE_BYTES 65536
#define GEMM_SMEM (2 * STAGE_BYTES)

__device__ __forceinline__ uint32_t swz(uint32_t row, uint32_t colbyte) {
    return row * 128 + (colbyte ^ ((row & 7) << 4));
}

__device__ __forceinline__ void ldg_a(float4* a, const float* __restrict__ A,
                                      int K, int m0, int k0, int tid) {
    #pragma unroll
    for (int l = 0; l < 8; l++) {
        int f = tid + 256 * l;
        int row = f >> 4, c4 = f & 15;
        a[l] = *(const float4*)(A + (size_t)(m0 + row) * K + k0 + c4 * 4);
    }
}

__device__ __forceinline__ void sts_a(const float4* a, uint32_t sAh, uint32_t sAl,
                                      int tid) {
    #pragma unroll
    for (int l = 0; l < 8; l++) {
        int f = tid + 256 * l;
        int row = f >> 4, c4 = f & 15;
        uint32_t off = swz(row, c4 * 8);
        float4 v = a[l];
        __nv_bfloat162 h0 = __floats2bfloat162_rn(v.x, v.y);
        __nv_bfloat162 h1 = __floats2bfloat162_rn(v.z, v.w);
        float2 f0 = __bfloat1622float2(h0);
        float2 f1 = __bfloat1622float2(h1);
        __nv_bfloat162 l0 = __floats2bfloat162_rn(v.x - f0.x, v.y - f0.y);
        __nv_bfloat162 l1 = __floats2bfloat162_rn(v.z - f1.x, v.w - f1.y);
        uint2 hw = make_uint2(*reinterpret_cast<const uint32_t*>(&h0),
                              *reinterpret_cast<const uint32_t*>(&h1));
        uint2 lw = make_uint2(*reinterpret_cast<const uint32_t*>(&l0),
                              *reinterpret_cast<const uint32_t*>(&l1));
        asm volatile("st.shared.v2.b32 [%0], {%1, %2};" :: "r"(sAh + off), "r"(hw.x), "r"(hw.y));
        asm volatile("st.shared.v2.b32 [%0], {%1, %2};" :: "r"(sAl + off), "r"(lw.x), "r"(lw.y));
    }
}

__device__ __forceinline__ void cpasync_b(uint32_t sBh, uint32_t sBl,
                                          const __nv_bfloat16* __restrict__ Bh,
                                          const __nv_bfloat16* __restrict__ Bl,
                                          int K, int n0, int k0, int tid) {
    #pragma unroll
    for (int l = 0; l < 4; l++) {
        int f = tid + 256 * l;
        int row = f >> 3, c8 = f & 7;
        uint32_t off = swz(row, c8 * 16);
        CP_ASYNC16(sBh + off, Bh + (size_t)(n0 + row) * K + k0 + c8 * 8);
        CP_ASYNC16(sBl + off, Bl + (size_t)(n0 + row) * K + k0 + c8 * 8);
    }
}

__device__ __forceinline__ void mma_gemm_body(const float* __restrict__ A,
                                              const __nv_bfloat16* __restrict__ Bh,
                                              const __nv_bfloat16* __restrict__ Bl,
                                              float* __restrict__ C,
                                              int N, int K,
                                              const float* __restrict__ bias,
                                              const float* __restrict__ res,
                                              int dogelu) {
    extern __shared__ char smem[];
    const uint32_t smem_base = smem_to_u32(smem);
    const int tid = threadIdx.x;
    const int wid = tid >> 5, lane = tid & 31;
    const int wm = wid >> 2, wn = wid & 3;   // 2 x 4 warp grid
    const int m0 = blockIdx.y * 128, n0 = blockIdx.x * 128;
    const int lr = lane & 15, lc = lane >> 4;

    float acc[4][4][4];
    #pragma unroll
    for (int i = 0; i < 4; i++)
        #pragma unroll
        for (int j = 0; j < 4; j++)
            #pragma unroll
            for (int p = 0; p < 4; p++) acc[i][j][p] = 0.f;

    const int T = K >> 6;
    float4 areg[8];

    // prologue: tile 0 into stage 0
    cpasync_b(smem_base + 32768, smem_base + 49152, Bh, Bl, K, n0, 0, tid);
    CP_ASYNC_COMMIT();
    ldg_a(areg, A, K, m0, 0, tid);
    sts_a(areg, smem_base, smem_base + 16384, tid);
    CP_ASYNC_WAIT0();
    __syncthreads();

    for (int t = 0; t < T; t++) {
        const int s = t & 1;
        const uint32_t sb = smem_base + s * STAGE_BYTES;
        const uint32_t nb = smem_base + (s ^ 1) * STAGE_BYTES;

        if (t + 1 < T) {
            cpasync_b(nb + 32768, nb + 49152, Bh, Bl, K, n0, (t + 1) * 64, tid);
            CP_ASYNC_COMMIT();
            ldg_a(areg, A, K, m0, (t + 1) * 64, tid);
        }

        const uint32_t sAh = sb, sAl = sb + 16384, sBh = sb + 32768, sBl = sb + 49152;
        #pragma unroll
        for (int kg = 0; kg < 4; kg++) {
            uint32_t ah[4][4], al[4][4];
            #pragma unroll
            for (int mt = 0; mt < 4; mt++) {
                uint32_t m = wm * 64 + mt * 16 + lr;
                uint32_t off = swz(m, kg * 32 + lc * 16);
                ldmx4(ah[mt], sAh + off);
                ldmx4(al[mt], sAl + off);
            }
            uint32_t bhf[2][4], blf[2][4];
            #pragma unroll
            for (int np = 0; np < 2; np++) {
                uint32_t n = wn * 32 + np * 16 + lr;
                uint32_t off = swz(n, kg * 32 + lc * 16);
                ldmx4(bhf[np], sBh + off);
                ldmx4(blf[np], sBl + off);
            }
            #pragma unroll
            for (int mt = 0; mt < 4; mt++) {
                #pragma unroll
                for (int nt = 0; nt < 4; nt++) {
                    int np = nt >> 1, u = nt & 1;
                    mma16816(acc[mt][nt], ah[mt], bhf[np][u], bhf[np][u + 2]);
                    mma16816(acc[mt][nt], ah[mt], blf[np][u], blf[np][u + 2]);
                    mma16816(acc[mt][nt], al[mt], bhf[np][u], bhf[np][u + 2]);
                }
            }
        }

        if (t + 1 < T) {
            sts_a(areg, nb, nb + 16384, tid);
            CP_ASYNC_WAIT0();
        }
        __syncthreads();
    }

    // epilogue: acc -> gmem with bias/gelu/res (float2 stores)
    #pragma unroll
    for (int mt = 0; mt < 4; mt++) {
        #pragma unroll
        for (int nt = 0; nt < 4; nt++) {
            int r0 = m0 + wm * 64 + mt * 16 + (lane >> 2);
            int c0 = n0 + wn * 32 + nt * 8 + (lane & 3) * 2;
            float bv0 = 0.f, bv1 = 0.f;
            if (bias) { bv0 = bias[c0]; bv1 = bias[c0 + 1]; }
            #pragma unroll
            for (int half = 0; half < 2; half++) {
                int r = r0 + half * 8;
                float v0 = acc[mt][nt][half * 2 + 0] + bv0;
                float v1 = acc[mt][nt][half * 2 + 1] + bv1;
                if (dogelu) { v0 = gelu_exact(v0); v1 = gelu_exact(v1); }
                if (res) {
                    float2 rr = *(const float2*)(res + (size_t)r * N + c0);
                    v0 += rr.x; v1 += rr.y;
                }
                float2 ov = make_float2(v0, v1);
                *(float2*)(C + (size_t)r * N + c0) = ov;
            }
        }
    }
}

__global__ void __launch_bounds__(256, 1)
mma_gemm(const float* __restrict__ A,
         const __nv_bfloat16* __restrict__ Bh, const __nv_bfloat16* __restrict__ Bl,
         float* __restrict__ C, int N, int K,
         const float* __restrict__ bias, const float* __restrict__ res, int dogelu) {
    mma_gemm_body(A, Bh, Bl, C, N, K, bias, res, dogelu);
}

__global__ void __launch_bounds__(256, 1)
mma_gemm_qkv(const float* __restrict__ A,
             const __nv_bfloat16* __restrict__ qh, const __nv_bfloat16* __restrict__ ql,
             const __nv_bfloat16* __restrict__ kh, const __nv_bfloat16* __restrict__ kl,
             const __nv_bfloat16* __restrict__ vh, const __nv_bfloat16* __restrict__ vl,
             float* __restrict__ q, float* __restrict__ k, float* __restrict__ v) {
    const __nv_bfloat16* Bh = (blockIdx.z == 0) ? qh : (blockIdx.z == 1) ? kh : vh;
    const __nv_bfloat16* Bl = (blockIdx.z == 0) ? ql : (blockIdx.z == 1) ? kl : vl;
    float* C = (blockIdx.z == 0) ? q : (blockIdx.z == 1) ? k : v;
    mma_gemm_body(A, Bh, Bl, C, DD, DD, nullptr, nullptr, 0);
}

// ---------------------------------------------------------------------------
// Flash attention (fp32 SIMT) — unchanged from R2
// ---------------------------------------------------------------------------
#define ATT_SMEM (64*132*4 + 64*68*4 + 64*68*4 + 64*132*4)

__global__ void __launch_bounds__(256, 2)
flash_attn_kernel(const float* __restrict__ Q, const float* __restrict__ K,
                  const float* __restrict__ V, float* __restrict__ O) {
    extern __shared__ float sm[];
    float* Qt = sm;
    float* Kt = Qt + 64 * 132;
    float* Vs = Kt + 64 * 68;
    float* Pt = Vs + 64 * 68;

    const int tid = threadIdx.x;
    const int tx = tid & 15;
    const int ty = tid >> 4;
    const int qt = blockIdx.x;
    const int h  = blockIdx.y & 15;
    const int b  = blockIdx.y >> 4;
    const size_t base = ((size_t)b * SS) * DD + (size_t)h * HDIM;

    #pragma unroll
    for (int l = 0; l < 8; l++) {
        int f = tid + 256 * l;
        int row = f >> 4;
        int c4  = f & 15;
        float4 v = *(const float4*)(Q + base + (size_t)(qt * 128 + row) * DD + c4 * 4);
        Qt[(c4 * 4 + 0) * 132 + row] = v.x;
        Qt[(c4 * 4 + 1) * 132 + row] = v.y;
        Qt[(c4 * 4 + 2) * 132 + row] = v.z;
        Qt[(c4 * 4 + 3) * 132 + row] = v.w;
    }

    float m_i[8], l_i[8], o[8][4];
    #pragma unroll
    for (int i = 0; i < 8; i++) {
        m_i[i] = -1e30f; l_i[i] = 0.f;
        #pragma unroll
        for (int j = 0; j < 4; j++) o[i][j] = 0.f;
    }
    __syncthreads();

    const int ktmax = 2 * qt + 1;
    for (int kt = 0; kt <= ktmax; kt++) {
        #pragma unroll
        for (int l = 0; l < 4; l++) {
            int f = tid + 256 * l;
            int row = f >> 4;
            int c4  = f & 15;
            float4 kv = *(const float4*)(K + base + (size_t)(kt * 64 + row) * DD + c4 * 4);
            Kt[(c4 * 4 + 0) * 68 + row] = kv.x;
            Kt[(c4 * 4 + 1) * 68 + row] = kv.y;
            Kt[(c4 * 4 + 2) * 68 + row] = kv.z;
            Kt[(c4 * 4 + 3) * 68 + row] = kv.w;
            float4 vv = *(const float4*)(V + base + (size_t)(kt * 64 + row) * DD + c4 * 4);
            *(float4*)(&Vs[row * 68 + c4 * 4]) = vv;
        }
        __syncthreads();

        float s[8][4];
        #pragma unroll
        for (int i = 0; i < 8; i++)
            #pragma unroll
            for (int j = 0; j < 4; j++) s[i][j] = 0.f;

        #pragma unroll
        for (int d = 0; d < 64; d++) {
            float a[8];
            *(float4*)(a)     = *(const float4*)(&Qt[d * 132 + ty * 8]);
            *(float4*)(a + 4) = *(const float4*)(&Qt[d * 132 + ty * 8 + 4]);
            float4 bb = *(const float4*)(&Kt[d * 68 + tx * 4]);
            #pragma unroll
            for (int i = 0; i < 8; i++) {
                s[i][0] = fmaf(a[i], bb.x, s[i][0]);
                s[i][1] = fmaf(a[i], bb.y, s[i][1]);
                s[i][2] = fmaf(a[i], bb.z, s[i][2]);
                s[i][3] = fmaf(a[i], bb.w, s[i][3]);
            }
        }

        const bool needmask = (kt >= 2 * qt);

        #pragma unroll
        for (int i = 0; i < 8; i++) {
            int qg = qt * 128 + ty * 8 + i;
            float rmax = -1e30f;
            #pragma unroll
            for (int j = 0; j < 4; j++) {
                float sv = s[i][j] * 0.125f;
                if (needmask && (kt * 64 + tx * 4 + j > qg)) sv = -1e30f;
                s[i][j] = sv;
                rmax = fmaxf(rmax, sv);
            }
            #pragma unroll
            for (int off = 1; off < 16; off <<= 1)
                rmax = fmaxf(rmax, __shfl_xor_sync(0xffffffffu, rmax, off));
            float mnew = fmaxf(m_i[i], rmax);
            float sc = __expf(m_i[i] - mnew);
            float rsum = 0.f;
            #pragma unroll
            for (int j = 0; j < 4; j++) {
                float p = __expf(s[i][j] - mnew);
                s[i][j] = p;
                rsum += p;
            }
            #pragma unroll
            for (int off = 1; off < 16; off <<= 1)
                rsum += __shfl_xor_sync(0xffffffffu, rsum, off);
            l_i[i] = l_i[i] * sc + rsum;
            m_i[i] = mnew;
            #pragma unroll
            for (int j = 0; j < 4; j++) {
                o[i][j] *= sc;
                Pt[(tx * 4 + j) * 132 + ty * 8 + i] = s[i][j];
            }
        }
        __syncthreads();

        #pragma unroll
        for (int kk = 0; kk < 64; kk++) {
            float a[8];
            *(float4*)(a)     = *(const float4*)(&Pt[kk * 132 + ty * 8]);
            *(float4*)(a + 4) = *(const float4*)(&Pt[kk * 132 + ty * 8 + 4]);
            float4 bb = *(const float4*)(&Vs[kk * 68 + tx * 4]);
            #pragma unroll
            for (int i = 0; i < 8; i++) {
                o[i][0] = fmaf(a[i], bb.x, o[i][0]);
                o[i][1] = fmaf(a[i], bb.y, o[i][1]);
                o[i][2] = fmaf(a[i], bb.z, o[i][2]);
                o[i][3] = fmaf(a[i], bb.w, o[i][3]);
            }
        }
        __syncthreads();
    }

    #pragma unroll
    for (int i = 0; i < 8; i++) {
        float inv = 1.0f / l_i[i];
        float4 ov;
        ov.x = o[i][0] * inv; ov.y = o[i][1] * inv;
        ov.z = o[i][2] * inv; ov.w = o[i][3] * inv;
        *(float4*)(O + base + (size_t)(qt * 128 + ty * 8 + i) * DD + tx * 4) = ov;
    }
}

// ---------------------------------------------------------------------------
// Launch
// ---------------------------------------------------------------------------
extern "C" void kernel_launch(void* const* d_in, const int* in_sizes, int n_in,
                              void* d_out, int out_size) {
    const float* x     = (const float*)d_in[0];
    const float* ln1_g = (const float*)d_in[1];
    const float* ln1_b = (const float*)d_in[2];
    const float* Wq    = (const float*)d_in[3];
    const float* Wk    = (const float*)d_in[4];
    const float* Wv    = (const float*)d_in[5];
    const float* Wo    = (const float*)d_in[6];
    const float* bo    = (const float*)d_in[7];
    const float* ln2_g = (const float*)d_in[8];
    const float* ln2_b = (const float*)d_in[9];
    const float* W1    = (const float*)d_in[10];
    const float* b1    = (const float*)d_in[11];
    const float* W2    = (const float*)d_in[12];
    const float* b2    = (const float*)d_in[13];
    float* out = (float*)d_out;

    float *h, *q, *k, *v, *ctx, *x2, *mid;
    cudaGetSymbolAddress((void**)&h,   g_h);
    cudaGetSymbolAddress((void**)&q,   g_q);
    cudaGetSymbolAddress((void**)&k,   g_k);
    cudaGetSymbolAddress((void**)&v,   g_v);
    cudaGetSymbolAddress((void**)&ctx, g_ctx);
    cudaGetSymbolAddress((void**)&x2,  g_x2);
    cudaGetSymbolAddress((void**)&mid, g_mid);

    __nv_bfloat16 *wqh, *wql, *wkh, *wkl, *wvh, *wvl, *woh, *wol, *w1h, *w1l, *w2h, *w2l;
    cudaGetSymbolAddress((void**)&wqh, g_wqh); cudaGetSymbolAddress((void**)&wql, g_wql);
    cudaGetSymbolAddress((void**)&wkh, g_wkh); cudaGetSymbolAddress((void**)&wkl, g_wkl);
    cudaGetSymbolAddress((void**)&wvh, g_wvh); cudaGetSymbolAddress((void**)&wvl, g_wvl);
    cudaGetSymbolAddress((void**)&woh, g_woh); cudaGetSymbolAddress((void**)&wol, g_wol);
    cudaGetSymbolAddress((void**)&w1h, g_w1h); cudaGetSymbolAddress((void**)&w1l, g_w1l);
    cudaGetSymbolAddress((void**)&w2h, g_w2h); cudaGetSymbolAddress((void**)&w2l, g_w2l);

    static int attr_set = 0;
    if (!attr_set) {
        cudaFuncSetAttribute(flash_attn_kernel,
                             cudaFuncAttributeMaxDynamicSharedMemorySize, ATT_SMEM);
        cudaFuncSetAttribute(mma_gemm,
                             cudaFuncAttributeMaxDynamicSharedMemorySize, GEMM_SMEM);
        cudaFuncSetAttribute(mma_gemm_qkv,
                             cudaFuncAttributeMaxDynamicSharedMemorySize, GEMM_SMEM);
        attr_set = 1;
    }

    const int M = MROWS;
    dim3 tb(32, 8);

    // 0. weight transpose + bf16x2 split
    wsplit_kernel<<<dim3(DD / 32, DD / 32), tb>>>(Wq, wqh, wql, DD, DD);
    wsplit_kernel<<<dim3(DD / 32, DD / 32), tb>>>(Wk, wkh, wkl, DD, DD);
    wsplit_kernel<<<dim3(DD / 32, DD / 32), tb>>>(Wv, wvh, wvl, DD, DD);
    wsplit_kernel<<<dim3(DD / 32, DD / 32), tb>>>(Wo, woh, wol, DD, DD);
    wsplit_kernel<<<dim3(DFF / 32, DD / 32), tb>>>(W1, w1h, w1l, DD, DFF);
    wsplit_kernel<<<dim3(DD / 32, DFF / 32), tb>>>(W2, w2h, w2l, DFF, DD);

    // 1. LN1
    ln_kernel<<<M, 256>>>(x, ln1_g, ln1_b, h);

    // 2. QKV projections (tensor cores via mma.sync)
    dim3 gQKV(DD / 128, M / 128, 3);
    mma_gemm_qkv<<<gQKV, 256, GEMM_SMEM>>>(h, wqh, wql, wkh, wkl, wvh, wvl, q, k, v);

    // 3. causal flash attention
    dim3 gA(SS / 128, BB * HH);
    flash_attn_kernel<<<gA, 256, ATT_SMEM>>>(q, k, v, ctx);

    // 4. output projection + bias + residual(x) -> x2
    dim3 gDD(DD / 128, M / 128);
    mma_gemm<<<gDD, 256, GEMM_SMEM>>>(ctx, woh, wol, x2, DD, DD, bo, x, 0);

    // 5. LN2
    ln_kernel<<<M, 256>>>(x2, ln2_g, ln2_b, h);

    // 6. W1 + b1 + exact GELU -> mid
    dim3 gFF(DFF / 128, M / 128);
    mma_gemm<<<gFF, 256, GEMM_SMEM>>>(h, w1h, w1l, mid, DFF, DD, b1, nullptr, 1);

    // 7. W2 + b2 + residual(x2) -> out
    mma_gemm<<<gDD, 256, GEMM_SMEM>>>(mid, w2h, w2l, out, DD, DFF, b2, x2, 0);
}

// round 5
// speedup vs baseline: 11.7158x; 1.0148x over previous
#include <cuda_runtime.h>
#include <cuda_bf16.h>
#include <math.h>
#include <cstdint>

// Problem constants
#define BB 2
#define SS 2048
#define DD 1024
#define HH 16
#define HDIM 64
#define DFF 4096
#define MROWS (BB * SS)   // 4096

// ---------------------------------------------------------------------------
// PTX helpers (non-arch-suffixed features only: ldmatrix, mma.sync, cp.async)
// ---------------------------------------------------------------------------
__device__ __forceinline__ uint32_t smem_to_u32(const void* smem_ptr) {
    uint32_t addr;
    asm("{ .reg .u64 tmp; cvta.to.shared.u64 tmp, %1; cvt.u32.u64 %0, tmp; }"
        : "=r"(addr) : "l"(smem_ptr));
    return addr;
}

__device__ __forceinline__ void ldmx4(uint32_t* r, uint32_t addr) {
    asm volatile("ldmatrix.sync.aligned.m8n8.x4.shared.b16 {%0,%1,%2,%3}, [%4];"
        : "=r"(r[0]), "=r"(r[1]), "=r"(r[2]), "=r"(r[3]) : "r"(addr));
}

__device__ __forceinline__ void mma16816(float* c, const uint32_t* a,
                                         uint32_t b0, uint32_t b1) {
    asm volatile(
        "mma.sync.aligned.m16n8k16.row.col.f32.bf16.bf16.f32 "
        "{%0,%1,%2,%3}, {%4,%5,%6,%7}, {%8,%9}, {%0,%1,%2,%3};"
        : "+f"(c[0]), "+f"(c[1]), "+f"(c[2]), "+f"(c[3])
        : "r"(a[0]), "r"(a[1]), "r"(a[2]), "r"(a[3]), "r"(b0), "r"(b1));
}

#define CP_ASYNC16(smem_u32, gptr) \
    asm volatile("cp.async.cg.shared.global [%0], [%1], 16;" \
        :: "r"(smem_u32), "l"(gptr))
#define CP_ASYNC_COMMIT() asm volatile("cp.async.commit_group;" ::: "memory")
#define CP_ASYNC_WAIT2()  asm volatile("cp.async.wait_group 2;" ::: "memory")

// ---------------------------------------------------------------------------
// Scratch (device globals; no allocations allowed)
// ---------------------------------------------------------------------------
__device__ float g_q  [MROWS * DD];
__device__ float g_k  [MROWS * DD];
__device__ float g_v  [MROWS * DD];
__device__ float g_x2 [MROWS * DD];
// bf16x2-split activations
__device__ __nv_bfloat16 g_hh  [MROWS * DD],  g_hl  [MROWS * DD];
__device__ __nv_bfloat16 g_ctxh[MROWS * DD],  g_ctxl[MROWS * DD];
__device__ __nv_bfloat16 g_midh[(size_t)MROWS * DFF], g_midl[(size_t)MROWS * DFF];
// Transposed + bf16x2-split weights: [N,K]
__device__ __nv_bfloat16 g_wqh[DD * DD],  g_wql[DD * DD];
__device__ __nv_bfloat16 g_wkh[DD * DD],  g_wkl[DD * DD];
__device__ __nv_bfloat16 g_wvh[DD * DD],  g_wvl[DD * DD];
__device__ __nv_bfloat16 g_woh[DD * DD],  g_wol[DD * DD];
__device__ __nv_bfloat16 g_w1h[DD * DFF], g_w1l[DD * DFF];
__device__ __nv_bfloat16 g_w2h[DFF * DD], g_w2l[DFF * DD];

// ---------------------------------------------------------------------------
// Weight transpose + bf16x2 split: W[K,N] fp32 -> Th,Tl [N,K] bf16
// ---------------------------------------------------------------------------
__global__ void wsplit_kernel(const float* __restrict__ W,
                              __nv_bfloat16* __restrict__ Th,
                              __nv_bfloat16* __restrict__ Tl,
                              int K, int N) {
    __shared__ float tile[32][33];
    int bx = blockIdx.x;  // N/32
    int by = blockIdx.y;  // K/32
    int tx = threadIdx.x; // 32
    int ty = threadIdx.y; // 8
    #pragma unroll
    for (int i = 0; i < 4; i++)
        tile[ty + 8 * i][tx] = W[(size_t)(by * 32 + ty + 8 * i) * N + bx * 32 + tx];
    __syncthreads();
    #pragma unroll
    for (int i = 0; i < 4; i++) {
        float v = tile[tx][ty + 8 * i];
        __nv_bfloat16 h = __float2bfloat16(v);
        __nv_bfloat16 l = __float2bfloat16(v - __bfloat162float(h));
        size_t o = (size_t)(bx * 32 + ty + 8 * i) * K + by * 32 + tx;
        Th[o] = h; Tl[o] = l;
    }
}

// ---------------------------------------------------------------------------
// float -> bf16 hi/lo pair helpers
// ---------------------------------------------------------------------------
__device__ __forceinline__ void split2(float a, float b, uint32_t& hw, uint32_t& lw) {
    __nv_bfloat162 h = __floats2bfloat162_rn(a, b);
    float2 f = __bfloat1622float2(h);
    __nv_bfloat162 l = __floats2bfloat162_rn(a - f.x, b - f.y);
    hw = *reinterpret_cast<const uint32_t*>(&h);
    lw = *reinterpret_cast<const uint32_t*>(&l);
}

// ---------------------------------------------------------------------------
// LayerNorm: writes bf16 hi/lo pair
// ---------------------------------------------------------------------------
__global__ void ln_kernel(const float* __restrict__ x,
                          const float* __restrict__ gamma,
                          const float* __restrict__ beta,
                          __nv_bfloat16* __restrict__ yh,
                          __nv_bfloat16* __restrict__ yl) {
    int row = blockIdx.x;
    int tid = threadIdx.x;  // 256
    const float4* xr = reinterpret_cast<const float4*>(x + (size_t)row * DD);
    float4 v = xr[tid];

    float s  = v.x + v.y + v.z + v.w;
    float sq = v.x * v.x + v.y * v.y + v.z * v.z + v.w * v.w;
    for (int o = 16; o > 0; o >>= 1) {
        s  += __shfl_down_sync(0xffffffffu, s,  o);
        sq += __shfl_down_sync(0xffffffffu, sq, o);
    }
    __shared__ float ws[8], wq[8];
    int lane = tid & 31, warp = tid >> 5;
    if (lane == 0) { ws[warp] = s; wq[warp] = sq; }
    __syncthreads();
    __shared__ float mu_s, rstd_s;
    if (tid == 0) {
        float ts = 0.f, tq = 0.f;
        #pragma unroll
        for (int i = 0; i < 8; i++) { ts += ws[i]; tq += wq[i]; }
        float mu  = ts * (1.0f / DD);
        float var = tq * (1.0f / DD) - mu * mu;
        mu_s = mu;
        rstd_s = rsqrtf(var + 1e-5f);
    }
    __syncthreads();
    float mu = mu_s, r = rstd_s;

    float4 g4 = reinterpret_cast<const float4*>(gamma)[tid];
    float4 b4 = reinterpret_cast<const float4*>(beta)[tid];
    float o0 = (v.x - mu) * r * g4.x + b4.x;
    float o1 = (v.y - mu) * r * g4.y + b4.y;
    float o2 = (v.z - mu) * r * g4.z + b4.z;
    float o3 = (v.w - mu) * r * g4.w + b4.w;
    uint2 hw, lw;
    split2(o0, o1, hw.x, lw.x);
    split2(o2, o3, hw.y, lw.y);
    *reinterpret_cast<uint2*>(yh + (size_t)row * DD + tid * 4) = hw;
    *reinterpret_cast<uint2*>(yl + (size_t)row * DD + tid * 4) = lw;
}

__device__ __forceinline__ float gelu_exact(float v) {
    return 0.5f * v * (1.0f + erff(v * 0.70710678118654752f));
}

// ---------------------------------------------------------------------------
// mma.sync bf16x2 GEMM: C = (Ah+Al)[M,K] @ (Bh+Bl)[N,K]^T (+bias)(gelu)(+res)
// CTA 128x128, BK=64, 8 warps (2M x 4N), 3-stage cp.async pipeline.
// Stage (64KB): Ah[16K] Al[16K] Bh[16K] Bl[16K], SW128 swizzle on 128B rows.
// mode: 0 = fp32 out; 1 = fp32 out + bias + res; 2 = bf16 hi/lo out + bias + gelu
// ---------------------------------------------------------------------------
#define STAGE_BYTES 65536
#define GEMM_SMEM (3 * STAGE_BYTES)

__device__ __forceinline__ uint32_t swz(uint32_t row, uint32_t colbyte) {
    return row * 128 + (colbyte ^ ((row & 7) << 4));
}

__device__ __forceinline__ void cpa_tile(uint32_t sdst, const __nv_bfloat16* __restrict__ g,
                                         int K, int r0, int k0, int tid) {
    #pragma unroll
    for (int l = 0; l < 4; l++) {
        int f = tid + 256 * l;        // 0..1023
        int row = f >> 3, c = f & 7;
        CP_ASYNC16(sdst + swz(row, c * 16), g + (size_t)(r0 + row) * K + k0 + c * 8);
    }
}

__device__ __forceinline__ void mma_gemm_body(const __nv_bfloat16* __restrict__ Ah,
                                              const __nv_bfloat16* __restrict__ Al,
                                              const __nv_bfloat16* __restrict__ Bh,
                                              const __nv_bfloat16* __restrict__ Bl,
                                              float* __restrict__ C,
                                              __nv_bfloat16* __restrict__ Ch,
                                              __nv_bfloat16* __restrict__ Cl,
                                              int N, int K,
                                              const float* __restrict__ bias,
                                              const float* __restrict__ res,
                                              int mode) {
    extern __shared__ char smem[];
    const uint32_t smem_base = smem_to_u32(smem);
    const int tid = threadIdx.x;
    const int wid = tid >> 5, lane = tid & 31;
    const int wm = wid >> 2, wn = wid & 3;   // 2 x 4 warp grid
    const int m0 = blockIdx.y * 128, n0 = blockIdx.x * 128;
    const int lr = lane & 15, lc = lane >> 4;

    float acc[4][4][4];
    #pragma unroll
    for (int i = 0; i < 4; i++)
        #pragma unroll
        for (int j = 0; j < 4; j++)
            #pragma unroll
            for (int p = 0; p < 4; p++) acc[i][j][p] = 0.f;

    const int T = K >> 6;

    auto load_tile = [&](int t, int s) {
        uint32_t sb = smem_base + s * STAGE_BYTES;
        int k0 = t * 64;
        cpa_tile(sb,         Ah, K, m0, k0, tid);
        cpa_tile(sb + 16384, Al, K, m0, k0, tid);
        cpa_tile(sb + 32768, Bh, K, n0, k0, tid);
        cpa_tile(sb + 49152, Bl, K, n0, k0, tid);
    };

    // prologue: 2 stages in flight
    load_tile(0, 0);
    CP_ASYNC_COMMIT();
    if (T > 1) load_tile(1, 1);
    CP_ASYNC_COMMIT();

    for (int t = 0; t < T; t++) {
        if (t + 2 < T) load_tile(t + 2, (t + 2) % 3);
        CP_ASYNC_COMMIT();               // empty group when no load -> keeps count uniform
        CP_ASYNC_WAIT2();                // group t complete
        __syncthreads();

        const uint32_t sb = smem_base + (t % 3) * STAGE_BYTES;
        const uint32_t sAh = sb, sAl = sb + 16384, sBh = sb + 32768, sBl = sb + 49152;
        #pragma unroll
        for (int kg = 0; kg < 4; kg++) {
            uint32_t ah[4][4], al[4][4];
            #pragma unroll
            for (int mt = 0; mt < 4; mt++) {
                uint32_t m = wm * 64 + mt * 16 + lr;
                uint32_t off = swz(m, kg * 32 + lc * 16);
                ldmx4(ah[mt], sAh + off);
                ldmx4(al[mt], sAl + off);
            }
            uint32_t bhf[2][4], blf[2][4];
            #pragma unroll
            for (int np = 0; np < 2; np++) {
                uint32_t n = wn * 32 + np * 16 + lr;
                uint32_t off = swz(n, kg * 32 + lc * 16);
                ldmx4(bhf[np], sBh + off);
                ldmx4(blf[np], sBl + off);
            }
            #pragma unroll
            for (int mt = 0; mt < 4; mt++) {
                #pragma unroll
                for (int nt = 0; nt < 4; nt++) {
                    int np = nt >> 1, u = nt & 1;
                    mma16816(acc[mt][nt], ah[mt], bhf[np][u], bhf[np][u + 2]);
                    mma16816(acc[mt][nt], ah[mt], blf[np][u], blf[np][u + 2]);
                    mma16816(acc[mt][nt], al[mt], bhf[np][u], bhf[np][u + 2]);
                }
            }
        }
        __syncthreads();
    }

    // epilogue
    #pragma unroll
    for (int mt = 0; mt < 4; mt++) {
        #pragma unroll
        for (int nt = 0; nt < 4; nt++) {
            int r0 = m0 + wm * 64 + mt * 16 + (lane >> 2);
            int c0 = n0 + wn * 32 + nt * 8 + (lane & 3) * 2;
            float bv0 = 0.f, bv1 = 0.f;
            if (mode != 0) { bv0 = bias[c0]; bv1 = bias[c0 + 1]; }
            #pragma unroll
            for (int half = 0; half < 2; half++) {
                int r = r0 + half * 8;
                float v0 = acc[mt][nt][half * 2 + 0] + bv0;
                float v1 = acc[mt][nt][half * 2 + 1] + bv1;
                if (mode == 2) {
                    v0 = gelu_exact(v0); v1 = gelu_exact(v1);
                    uint32_t hw, lw;
                    split2(v0, v1, hw, lw);
                    *reinterpret_cast<uint32_t*>(Ch + (size_t)r * N + c0) = hw;
                    *reinterpret_cast<uint32_t*>(Cl + (size_t)r * N + c0) = lw;
                } else {
                    if (mode == 1) {
                        float2 rr = *(const float2*)(res + (size_t)r * N + c0);
                        v0 += rr.x; v1 += rr.y;
                    }
                    *(float2*)(C + (size_t)r * N + c0) = make_float2(v0, v1);
                }
            }
        }
    }
}

__global__ void __launch_bounds__(256, 1)
mma_gemm(const __nv_bfloat16* __restrict__ Ah, const __nv_bfloat16* __restrict__ Al,
         const __nv_bfloat16* __restrict__ Bh, const __nv_bfloat16* __restrict__ Bl,
         float* __restrict__ C, __nv_bfloat16* __restrict__ Ch,
         __nv_bfloat16* __restrict__ Cl, int N, int K,
         const float* __restrict__ bias, const float* __restrict__ res, int mode) {
    mma_gemm_body(Ah, Al, Bh, Bl, C, Ch, Cl, N, K, bias, res, mode);
}

__global__ void __launch_bounds__(256, 1)
mma_gemm_qkv(const __nv_bfloat16* __restrict__ Ah, const __nv_bfloat16* __restrict__ Al,
             const __nv_bfloat16* __restrict__ qh, const __nv_bfloat16* __restrict__ ql,
             const __nv_bfloat16* __restrict__ kh, const __nv_bfloat16* __restrict__ kl,
             const __nv_bfloat16* __restrict__ vh, const __nv_bfloat16* __restrict__ vl,
             float* __restrict__ q, float* __restrict__ k, float* __restrict__ v) {
    const __nv_bfloat16* Bh = (blockIdx.z == 0) ? qh : (blockIdx.z == 1) ? kh : vh;
    const __nv_bfloat16* Bl = (blockIdx.z == 0) ? ql : (blockIdx.z == 1) ? kl : vl;
    float* C = (blockIdx.z == 0) ? q : (blockIdx.z == 1) ? k : v;
    mma_gemm_body(Ah, Al, Bh, Bl, C, nullptr, nullptr, DD, DD, nullptr, nullptr, 0);
}

// ---------------------------------------------------------------------------
// Flash attention (fp32 SIMT); epilogue writes ctx as bf16 hi/lo pair.
// ---------------------------------------------------------------------------
#define ATT_SMEM (64*132*4 + 64*68*4 + 64*68*4 + 64*132*4)

__global__ void __launch_bounds__(256, 2)
flash_attn_kernel(const float* __restrict__ Q, const float* __restrict__ K,
                  const float* __restrict__ V,
                  __nv_bfloat16* __restrict__ Oh, __nv_bfloat16* __restrict__ Ol) {
    extern __shared__ float sm[];
    float* Qt = sm;
    float* Kt = Qt + 64 * 132;
    float* Vs = Kt + 64 * 68;
    float* Pt = Vs + 64 * 68;

    const int tid = threadIdx.x;
    const int tx = tid & 15;
    const int ty = tid >> 4;
    const int qt = blockIdx.x;
    const int h  = blockIdx.y & 15;
    const int b  = blockIdx.y >> 4;
    const size_t base = ((size_t)b * SS) * DD + (size_t)h * HDIM;

    #pragma unroll
    for (int l = 0; l < 8; l++) {
        int f = tid + 256 * l;
        int row = f >> 4;
        int c4  = f & 15;
        float4 v = *(const float4*)(Q + base + (size_t)(qt * 128 + row) * DD + c4 * 4);
        Qt[(c4 * 4 + 0) * 132 + row] = v.x;
        Qt[(c4 * 4 + 1) * 132 + row] = v.y;
        Qt[(c4 * 4 + 2) * 132 + row] = v.z;
        Qt[(c4 * 4 + 3) * 132 + row] = v.w;
    }

    float m_i[8], l_i[8], o[8][4];
    #pragma unroll
    for (int i = 0; i < 8; i++) {
        m_i[i] = -1e30f; l_i[i] = 0.f;
        #pragma unroll
        for (int j = 0; j < 4; j++) o[i][j] = 0.f;
    }
    __syncthreads();

    const int ktmax = 2 * qt + 1;
    for (int kt = 0; kt <= ktmax; kt++) {
        #pragma unroll
        for (int l = 0; l < 4; l++) {
            int f = tid + 256 * l;
            int row = f >> 4;
            int c4  = f & 15;
            float4 kv = *(const float4*)(K + base + (size_t)(kt * 64 + row) * DD + c4 * 4);
            Kt[(c4 * 4 + 0) * 68 + row] = kv.x;
            Kt[(c4 * 4 + 1) * 68 + row] = kv.y;
            Kt[(c4 * 4 + 2) * 68 + row] = kv.z;
            Kt[(c4 * 4 + 3) * 68 + row] = kv.w;
            float4 vv = *(const float4*)(V + base + (size_t)(kt * 64 + row) * DD + c4 * 4);
            *(float4*)(&Vs[row * 68 + c4 * 4]) = vv;
        }
        __syncthreads();

        float s[8][4];
        #pragma unroll
        for (int i = 0; i < 8; i++)
            #pragma unroll
            for (int j = 0; j < 4; j++) s[i][j] = 0.f;

        #pragma unroll
        for (int d = 0; d < 64; d++) {
            float a[8];
            *(float4*)(a)     = *(const float4*)(&Qt[d * 132 + ty * 8]);
            *(float4*)(a + 4) = *(const float4*)(&Qt[d * 132 + ty * 8 + 4]);
            float4 bb = *(const float4*)(&Kt[d * 68 + tx * 4]);
            #pragma unroll
            for (int i = 0; i < 8; i++) {
                s[i][0] = fmaf(a[i], bb.x, s[i][0]);
                s[i][1] = fmaf(a[i], bb.y, s[i][1]);
                s[i][2] = fmaf(a[i], bb.z, s[i][2]);
                s[i][3] = fmaf(a[i], bb.w, s[i][3]);
            }
        }

        const bool needmask = (kt >= 2 * qt);

        #pragma unroll
        for (int i = 0; i < 8; i++) {
            int qg = qt * 128 + ty * 8 + i;
            float rmax = -1e30f;
            #pragma unroll
            for (int j = 0; j < 4; j++) {
                float sv = s[i][j] * 0.125f;
                if (needmask && (kt * 64 + tx * 4 + j > qg)) sv = -1e30f;
                s[i][j] = sv;
                rmax = fmaxf(rmax, sv);
            }
            #pragma unroll
            for (int off = 1; off < 16; off <<= 1)
                rmax = fmaxf(rmax, __shfl_xor_sync(0xffffffffu, rmax, off));
            float mnew = fmaxf(m_i[i], rmax);
            float sc = __expf(m_i[i] - mnew);
            float rsum = 0.f;
            #pragma unroll
            for (int j = 0; j < 4; j++) {
                float p = __expf(s[i][j] - mnew);
                s[i][j] = p;
                rsum += p;
            }
            #pragma unroll
            for (int off = 1; off < 16; off <<= 1)
                rsum += __shfl_xor_sync(0xffffffffu, rsum, off);
            l_i[i] = l_i[i] * sc + rsum;
            m_i[i] = mnew;
            #pragma unroll
            for (int j = 0; j < 4; j++) {
                o[i][j] *= sc;
                Pt[(tx * 4 + j) * 132 + ty * 8 + i] = s[i][j];
            }
        }
        __syncthreads();

        #pragma unroll
        for (int kk = 0; kk < 64; kk++) {
            float a[8];
            *(float4*)(a)     = *(const float4*)(&Pt[kk * 132 + ty * 8]);
            *(float4*)(a + 4) = *(const float4*)(&Pt[kk * 132 + ty * 8 + 4]);
            float4 bb = *(const float4*)(&Vs[kk * 68 + tx * 4]);
            #pragma unroll
            for (int i = 0; i < 8; i++) {
                o[i][0] = fmaf(a[i], bb.x, o[i][0]);
                o[i][1] = fmaf(a[i], bb.y, o[i][1]);
                o[i][2] = fmaf(a[i], bb.z, o[i][2]);
                o[i][3] = fmaf(a[i], bb.w, o[i][3]);
            }
        }
        __syncthreads();
    }

    #pragma unroll
    for (int i = 0; i < 8; i++) {
        float inv = 1.0f / l_i[i];
        float v0 = o[i][0] * inv, v1 = o[i][1] * inv;
        float v2 = o[i][2] * inv, v3 = o[i][3] * inv;
        uint2 hw, lw;
        split2(v0, v1, hw.x, lw.x);
        split2(v2, v3, hw.y, lw.y);
        size_t off = base + (size_t)(qt * 128 + ty * 8 + i) * DD + tx * 4;
        *reinterpret_cast<uint2*>(Oh + off) = hw;
        *reinterpret_cast<uint2*>(Ol + off) = lw;
    }
}

// ---------------------------------------------------------------------------
// Launch
// ---------------------------------------------------------------------------
extern "C" void kernel_launch(void* const* d_in, const int* in_sizes, int n_in,
                              void* d_out, int out_size) {
    const float* x     = (const float*)d_in[0];
    const float* ln1_g = (const float*)d_in[1];
    const float* ln1_b = (const float*)d_in[2];
    const float* Wq    = (const float*)d_in[3];
    const float* Wk    = (const float*)d_in[4];
    const float* Wv    = (const float*)d_in[5];
    const float* Wo    = (const float*)d_in[6];
    const float* bo    = (const float*)d_in[7];
    const float* ln2_g = (const float*)d_in[8];
    const float* ln2_b = (const float*)d_in[9];
    const float* W1    = (const float*)d_in[10];
    const float* b1    = (const float*)d_in[11];
    const float* W2    = (const float*)d_in[12];
    const float* b2    = (const float*)d_in[13];
    float* out = (float*)d_out;

    float *q, *k, *v, *x2;
    cudaGetSymbolAddress((void**)&q,   g_q);
    cudaGetSymbolAddress((void**)&k,   g_k);
    cudaGetSymbolAddress((void**)&v,   g_v);
    cudaGetSymbolAddress((void**)&x2,  g_x2);
    __nv_bfloat16 *hh, *hl, *ctxh, *ctxl, *midh, *midl;
    cudaGetSymbolAddress((void**)&hh,   g_hh);   cudaGetSymbolAddress((void**)&hl,   g_hl);
    cudaGetSymbolAddress((void**)&ctxh, g_ctxh); cudaGetSymbolAddress((void**)&ctxl, g_ctxl);
    cudaGetSymbolAddress((void**)&midh, g_midh); cudaGetSymbolAddress((void**)&midl, g_midl);

    __nv_bfloat16 *wqh, *wql, *wkh, *wkl, *wvh, *wvl, *woh, *wol, *w1h, *w1l, *w2h, *w2l;
    cudaGetSymbolAddress((void**)&wqh, g_wqh); cudaGetSymbolAddress((void**)&wql, g_wql);
    cudaGetSymbolAddress((void**)&wkh, g_wkh); cudaGetSymbolAddress((void**)&wkl, g_wkl);
    cudaGetSymbolAddress((void**)&wvh, g_wvh); cudaGetSymbolAddress((void**)&wvl, g_wvl);
    cudaGetSymbolAddress((void**)&woh, g_woh); cudaGetSymbolAddress((void**)&wol, g_wol);
    cudaGetSymbolAddress((void**)&w1h, g_w1h); cudaGetSymbolAddress((void**)&w1l, g_w1l);
    cudaGetSymbolAddress((void**)&w2h, g_w2h); cudaGetSymbolAddress((void**)&w2l, g_w2l);

    static int attr_set = 0;
    if (!attr_set) {
        cudaFuncSetAttribute(flash_attn_kernel,
                             cudaFuncAttributeMaxDynamicSharedMemorySize, ATT_SMEM);
        cudaFuncSetAttribute(mma_gemm,
                             cudaFuncAttributeMaxDynamicSharedMemorySize, GEMM_SMEM);
        cudaFuncSetAttribute(mma_gemm_qkv,
                             cudaFuncAttributeMaxDynamicSharedMemorySize, GEMM_SMEM);
        attr_set = 1;
    }

    const int M = MROWS;
    dim3 tb(32, 8);

    // 0. weight transpose + bf16x2 split
    wsplit_kernel<<<dim3(DD / 32, DD / 32), tb>>>(Wq, wqh, wql, DD, DD);
    wsplit_kernel<<<dim3(DD / 32, DD / 32), tb>>>(Wk, wkh, wkl, DD, DD);
    wsplit_kernel<<<dim3(DD / 32, DD / 32), tb>>>(Wv, wvh, wvl, DD, DD);
    wsplit_kernel<<<dim3(DD / 32, DD / 32), tb>>>(Wo, woh, wol, DD, DD);
    wsplit_kernel<<<dim3(DFF / 32, DD / 32), tb>>>(W1, w1h, w1l, DD, DFF);
    wsplit_kernel<<<dim3(DD / 32, DFF / 32), tb>>>(W2, w2h, w2l, DFF, DD);

    // 1. LN1 -> (hh, hl)
    ln_kernel<<<M, 256>>>(x, ln1_g, ln1_b, hh, hl);

    // 2. QKV projections
    dim3 gQKV(DD / 128, M / 128, 3);
    mma_gemm_qkv<<<gQKV, 256, GEMM_SMEM>>>(hh, hl, wqh, wql, wkh, wkl, wvh, wvl, q, k, v);

    // 3. causal flash attention -> (ctxh, ctxl)
    dim3 gA(SS / 128, BB * HH);
    flash_attn_kernel<<<gA, 256, ATT_SMEM>>>(q, k, v, ctxh, ctxl);

    // 4. output projection + bias + residual(x) -> x2
    dim3 gDD(DD / 128, M / 128);
    mma_gemm<<<gDD, 256, GEMM_SMEM>>>(ctxh, ctxl, woh, wol, x2, nullptr, nullptr,
                                      DD, DD, bo, x, 1);

    // 5. LN2 -> (hh, hl)
    ln_kernel<<<M, 256>>>(x2, ln2_g, ln2_b, hh, hl);

    // 6. W1 + b1 + GELU -> (midh, midl)
    dim3 gFF(DFF / 128, M / 128);
    mma_gemm<<<gFF, 256, GEMM_SMEM>>>(hh, hl, w1h, w1l, nullptr, midh, midl,
                                      DFF, DD, b1, nullptr, 2);

    // 7. W2 + b2 + residual(x2) -> out
    mma_gemm<<<gDD, 256, GEMM_SMEM>>>(midh, midl, w2h, w2l, out, nullptr, nullptr,
                                      DD, DFF, b2, x2, 1);
}